// round 8
// baseline (speedup 1.0000x reference)
#include <cuda_runtime.h>
#include <cuda_bf16.h>
#include <math.h>

// Problem constants (fixed by the reference)
#define B_DIM 128
#define S_DIM 512
#define K_DIM 137
#define D_DIM (2 * K_DIM)      // 274
#define NCONN (K_DIM - 1)      // 136
#define TILE_S 16                            // timesteps per block
#define WARPS_PER_BLOCK TILE_S               // one warp per timestep
#define THREADS (WARPS_PER_BLOCK * 32)       // 512
#define TILES_PER_B (S_DIM / TILE_S)         // 32
#define N_BLOCKS (B_DIM * TILES_PER_B)       // 4096
#define THREADS_F 256

#define FULL_MASK 0xffffffffu

// SMEM tile sizes (floats). Copy loops round byte counts up to 16B, so pad.
#define PRED_TILE_F (TILE_S * D_DIM)             // 4384 (multiple of 4)
#define T_TILE_F    ((TILE_S + 1) * K_DIM)       // 2329
#define T_TILE_F_PAD 2332                        // ceil to multiple of 4

// Allocation-free scratch. Written unconditionally by every block each run.
__device__ float2 g_partials[N_BLOCKS];

// Block = (b, s0..s0+15). Stage contiguous pred/tgt tiles into SMEM with
// float4 copies, then per-warp register/shuffle compute (R4 structure).
__global__ __launch_bounds__(THREADS) void t2p_main_kernel(
    const float* __restrict__ pred,   // [128, 512, 274]
    const float* __restrict__ tgt,    // [128, 2, 512, 137]
    const int*   __restrict__ tlen)   // [128]
{
    __shared__ __align__(16) float s_pred[PRED_TILE_F];
    __shared__ __align__(16) float s_t0[T_TILE_F_PAD];
    __shared__ __align__(16) float s_t1[T_TILE_F_PAD];
    __shared__ float s_pose[WARPS_PER_BLOCK];
    __shared__ float s_bone[WARPS_PER_BLOCK];

    const int warp = threadIdx.x >> 5;
    const int lane = threadIdx.x & 31;
    const int b  = blockIdx.x >> 5;          // blockIdx / 32
    const int s0 = (blockIdx.x & 31) << 4;   // tile start timestep

    const int L = __ldg(&tlen[b]);
    const bool tile_live = (s0 < L);

    float pose_sum = 0.0f;
    float bone_sum = 0.0f;

    if (tile_live) {
        // ---- Stage tiles (contiguous global runs, float4) ----
        const int n_p = min(TILE_S, L - s0);       // pred rows needed (bone)
        const int n_t = min(TILE_S + 1, L - s0);   // tgt rows needed (<= L-1 index)

        {
            const float4* __restrict__ src =
                (const float4*)(pred + (size_t)(b * S_DIM + s0) * D_DIM);
            float4* dst = (float4*)s_pred;
            const int n4 = (n_p * D_DIM + 3) >> 2;
            for (int i = threadIdx.x; i < n4; i += THREADS) dst[i] = src[i];
        }
        {
            const float4* __restrict__ src =
                (const float4*)(tgt + ((size_t)(2 * b) * S_DIM + s0) * K_DIM);
            float4* dst = (float4*)s_t0;
            const int n4 = (n_t * K_DIM + 3) >> 2;
            for (int i = threadIdx.x; i < n4; i += THREADS) dst[i] = src[i];
        }
        {
            const float4* __restrict__ src =
                (const float4*)(tgt + ((size_t)(2 * b + 1) * S_DIM + s0) * K_DIM);
            float4* dst = (float4*)s_t1;
            const int n4 = (n_t * K_DIM + 3) >> 2;
            for (int i = threadIdx.x; i < n4; i += THREADS) dst[i] = src[i];
        }
        __syncthreads();

        // ---- Per-warp compute from SMEM (R4 register/shuffle structure) ----
        const int s = s0 + warp;
        const bool bone_valid = (s < L);
        const bool pose_valid = (s < L - 1);

        if (bone_valid) {
            const float2* __restrict__ p2 = (const float2*)(s_pred + warp * D_DIM);
            const float*  __restrict__ t0 = s_t0 + warp * K_DIM;
            const float*  __restrict__ t1 = s_t1 + warp * K_DIM;

            float ex[5], ey[5];

            #pragma unroll
            for (int j = 0; j < 4; j++) {
                const int k = lane + 32 * j;
                float2 p = p2[k];
                ex[j] = p.x - t0[k];
                ey[j] = p.y - t1[k];
                if (pose_valid) {
                    pose_sum += fabsf(p.x - t0[k + K_DIM])
                              + fabsf(p.y - t1[k + K_DIM]);
                }
            }
            ex[4] = 0.0f; ey[4] = 0.0f;
            if (lane < 9) {
                const int k = 128 + lane;
                float2 p = p2[k];
                ex[4] = p.x - t0[k];
                ey[4] = p.y - t1[k];
                if (pose_valid) {
                    pose_sum += fabsf(p.x - t0[k + K_DIM])
                              + fabsf(p.y - t1[k + K_DIM]);
                }
            }

            // Bone: d[k] = e[k+1] - e[k] via shuffles.
            #pragma unroll
            for (int j = 0; j < 4; j++) {
                float nx_dn = __shfl_down_sync(FULL_MASK, ex[j], 1);
                float ny_dn = __shfl_down_sync(FULL_MASK, ey[j], 1);
                float nx_w0 = __shfl_sync(FULL_MASK, ex[j + 1], 0);
                float ny_w0 = __shfl_sync(FULL_MASK, ey[j + 1], 0);
                float nx = (lane == 31) ? nx_w0 : nx_dn;
                float ny = (lane == 31) ? ny_w0 : ny_dn;
                float dx = nx - ex[j];
                float dy = ny - ey[j];
                bone_sum = fmaf(dx, dx, bone_sum);
                bone_sum = fmaf(dy, dy, bone_sum);
            }
            {   // k = 128..135 diffs on lanes 0..7
                float nx_dn = __shfl_down_sync(FULL_MASK, ex[4], 1);
                float ny_dn = __shfl_down_sync(FULL_MASK, ey[4], 1);
                if (lane < 8) {
                    float dx = nx_dn - ex[4];
                    float dy = ny_dn - ey[4];
                    bone_sum = fmaf(dx, dx, bone_sum);
                    bone_sum = fmaf(dy, dy, bone_sum);
                }
            }
        }
    }

    // Warp reduce
    #pragma unroll
    for (int o = 16; o > 0; o >>= 1) {
        pose_sum += __shfl_xor_sync(FULL_MASK, pose_sum, o);
        bone_sum += __shfl_xor_sync(FULL_MASK, bone_sum, o);
    }
    if (lane == 0) {
        s_pose[warp] = pose_sum;
        s_bone[warp] = bone_sum;
    }
    __syncthreads();

    if (threadIdx.x == 0) {
        float ps = 0.0f, bs = 0.0f;
        #pragma unroll
        for (int w = 0; w < WARPS_PER_BLOCK; w++) {
            ps += s_pose[w];
            bs += s_bone[w];
        }
        g_partials[blockIdx.x] = make_float2(ps, bs);
    }
}

// Finalize with PDL: prologue overlaps main; body gated on grid dependency.
__global__ __launch_bounds__(THREADS_F) void t2p_finalize_kernel(
    const int* __restrict__ tlen,
    float*     __restrict__ out)
{
    __shared__ float r_p[THREADS_F / 32];
    __shared__ float r_b[THREADS_F / 32];
    __shared__ int   s_len;

    const int warp = threadIdx.x >> 5;
    const int lane = threadIdx.x & 31;

    // Pre-sync work: independent of main kernel output
    if (warp == 0) {
        int lsum = 0;
        #pragma unroll
        for (int i = 0; i < 4; i++) lsum += __ldg(&tlen[lane + 32 * i]);
        #pragma unroll
        for (int o = 16; o > 0; o >>= 1)
            lsum += __shfl_xor_sync(FULL_MASK, lsum, o);
        if (lane == 0) s_len = lsum;
    }

    cudaGridDependencySynchronize();

    const float4* __restrict__ p4 = (const float4*)g_partials;  // 2048 float4

    float dp = 0.0f, db = 0.0f;
    #pragma unroll
    for (int i = 0; i < 8; i++) {
        float4 v = __ldg(&p4[threadIdx.x + THREADS_F * i]);
        dp += v.x + v.z;
        db += v.y + v.w;
    }
    #pragma unroll
    for (int o = 16; o > 0; o >>= 1) {
        dp += __shfl_xor_sync(FULL_MASK, dp, o);
        db += __shfl_xor_sync(FULL_MASK, db, o);
    }
    if (lane == 0) {
        r_p[warp] = dp;
        r_b[warp] = db;
    }
    __syncthreads();

    if (threadIdx.x == 0) {
        float pose_acc = 0.0f, bone_acc = 0.0f;
        #pragma unroll
        for (int w = 0; w < THREADS_F / 32; w++) {
            pose_acc += r_p[w];
            bone_acc += r_b[w];
        }
        float len_total = (float)s_len;
        float mask_sum  = len_total;                    // sum(L)
        float pose_den  = len_total - (float)B_DIM;     // sum(L-1)

        float pose_loss = pose_acc / ((float)D_DIM * pose_den);
        float bone_loss = bone_acc * 0.5f / (((float)NCONN + 1e-8f) * mask_sum);
        float total     = pose_loss + 0.1f * bone_loss;

        out[0] = total;
        out[1] = pose_loss;
        out[2] = bone_loss;
    }
}

extern "C" void kernel_launch(void* const* d_in, const int* in_sizes, int n_in,
                              void* d_out, int out_size) {
    const float* pred = (const float*)d_in[0];   // [128, 512, 274] f32
    const float* tgt  = (const float*)d_in[1];   // [128, 2, 512, 137] f32
    const int*   tlen = (const int*)d_in[2];     // [128] i32
    float* out = (float*)d_out;                  // [3] f32: total, pose, bone

    t2p_main_kernel<<<N_BLOCKS, THREADS>>>(pred, tgt, tlen);

    // PDL launch: finalize prologue overlaps main.
    cudaLaunchConfig_t cfg = {};
    cfg.gridDim  = dim3(1, 1, 1);
    cfg.blockDim = dim3(THREADS_F, 1, 1);
    cfg.dynamicSmemBytes = 0;
    cfg.stream = 0;
    cudaLaunchAttribute attr[1];
    attr[0].id = cudaLaunchAttributeProgrammaticStreamSerialization;
    attr[0].val.programmaticStreamSerializationAllowed = 1;
    cfg.attrs = attr;
    cfg.numAttrs = 1;
    cudaLaunchKernelEx(&cfg, t2p_finalize_kernel, tlen, (float*)out);
}